// round 11
// baseline (speedup 1.0000x reference)
#include <cuda_runtime.h>
#include <cuda_fp16.h>

#define B_    4
#define N_    2048
#define F_IN  256
#define H_    8
#define F_OUT 64
#define HF    (H_ * F_OUT)       // 512
#define DEG_CAP 256

// Scratch (device globals: allocation-free per harness rules)
__device__ __half g_h16[(size_t)B_ * N_ * HF];     // [b][n][h][o], fp16
__device__ float  g_atts2[B_ * N_ * H_];           // [b][n][h]
__device__ float  g_attn2[B_ * N_ * H_];           // [b][n][h]

// -------------------------------------------------------------------------
// Kernel 1: h = X @ W, TWO heads per CTA (64 rows x 128 cols), 4x8 micro-tile.
// Fused epilogue: att logits from fp32 accs (exact) + fp16 h store [b][n][h][o].
// -------------------------------------------------------------------------
__global__ __launch_bounds__(256) void gemm_h_kernel(const float* __restrict__ X,
                                                     const float* __restrict__ W,
                                                     const float* __restrict__ a_self,
                                                     const float* __restrict__ a_neigh) {
    const int hp   = blockIdx.y;               // head pair: heads 2hp, 2hp+1
    const int b    = blockIdx.x >> 5;
    const int n0   = (blockIdx.x & 31) * 64;

    __shared__ float Xs[64][20];               // 64 rows x 16-k tile, padded
    __shared__ float Ws[16][128];              // 16 k x (2 heads * 64 cols)

    const int t  = threadIdx.x;
    const int ty = t >> 4;                     // 0..15 -> rows ty*4..+3
    const int tx = t & 15;                     // 0..15 -> cols tx*8..+7

    const float* Xb = X + ((size_t)b * N_ + n0) * F_IN;
    const float* W0 = W + (size_t)(2 * hp)     * F_IN * F_OUT;
    const float* W1 = W + (size_t)(2 * hp + 1) * F_IN * F_OUT;

    float acc[4][8] = {};

    for (int k0 = 0; k0 < F_IN; k0 += 16) {
        {   // X tile: 64 x 16
            int row = t >> 2;
            int q   = (t & 3) * 4;
            float4 v = *(const float4*)(Xb + (size_t)row * F_IN + k0 + q);
            *(float4*)&Xs[row][q] = v;
        }
        {   // W tile: both heads, 16 x 64 each
            int r = t >> 4;
            int q = (t & 15) * 4;
            *(float4*)&Ws[r][q]      = *(const float4*)(W0 + (size_t)(k0 + r) * F_OUT + q);
            *(float4*)&Ws[r][64 + q] = *(const float4*)(W1 + (size_t)(k0 + r) * F_OUT + q);
        }
        __syncthreads();

        #pragma unroll
        for (int k = 0; k < 16; k++) {
            float4 bv0 = *(float4*)&Ws[k][tx * 8];
            float4 bv1 = *(float4*)&Ws[k][tx * 8 + 4];
            float a0 = Xs[ty * 4 + 0][k];
            float a1 = Xs[ty * 4 + 1][k];
            float a2 = Xs[ty * 4 + 2][k];
            float a3 = Xs[ty * 4 + 3][k];
            acc[0][0] = fmaf(a0, bv0.x, acc[0][0]); acc[0][1] = fmaf(a0, bv0.y, acc[0][1]);
            acc[0][2] = fmaf(a0, bv0.z, acc[0][2]); acc[0][3] = fmaf(a0, bv0.w, acc[0][3]);
            acc[0][4] = fmaf(a0, bv1.x, acc[0][4]); acc[0][5] = fmaf(a0, bv1.y, acc[0][5]);
            acc[0][6] = fmaf(a0, bv1.z, acc[0][6]); acc[0][7] = fmaf(a0, bv1.w, acc[0][7]);
            acc[1][0] = fmaf(a1, bv0.x, acc[1][0]); acc[1][1] = fmaf(a1, bv0.y, acc[1][1]);
            acc[1][2] = fmaf(a1, bv0.z, acc[1][2]); acc[1][3] = fmaf(a1, bv0.w, acc[1][3]);
            acc[1][4] = fmaf(a1, bv1.x, acc[1][4]); acc[1][5] = fmaf(a1, bv1.y, acc[1][5]);
            acc[1][6] = fmaf(a1, bv1.z, acc[1][6]); acc[1][7] = fmaf(a1, bv1.w, acc[1][7]);
            acc[2][0] = fmaf(a2, bv0.x, acc[2][0]); acc[2][1] = fmaf(a2, bv0.y, acc[2][1]);
            acc[2][2] = fmaf(a2, bv0.z, acc[2][2]); acc[2][3] = fmaf(a2, bv0.w, acc[2][3]);
            acc[2][4] = fmaf(a2, bv1.x, acc[2][4]); acc[2][5] = fmaf(a2, bv1.y, acc[2][5]);
            acc[2][6] = fmaf(a2, bv1.z, acc[2][6]); acc[2][7] = fmaf(a2, bv1.w, acc[2][7]);
            acc[3][0] = fmaf(a3, bv0.x, acc[3][0]); acc[3][1] = fmaf(a3, bv0.y, acc[3][1]);
            acc[3][2] = fmaf(a3, bv0.z, acc[3][2]); acc[3][3] = fmaf(a3, bv0.w, acc[3][3]);
            acc[3][4] = fmaf(a3, bv1.x, acc[3][4]); acc[3][5] = fmaf(a3, bv1.y, acc[3][5]);
            acc[3][6] = fmaf(a3, bv1.z, acc[3][6]); acc[3][7] = fmaf(a3, bv1.w, acc[3][7]);
        }
        __syncthreads();
    }

    // thread's 8 cols live in one head: head = 2hp + (tx>>3), in-head base (tx&7)*8
    const int head = 2 * hp + (tx >> 3);
    const int oc   = (tx & 7) * 8;

    // ---- epilogue 1: attention logits (reduce over the 8-lane tx&7 group) ----
    {
        const float* as = a_self  + head * F_OUT + oc;
        const float* an = a_neigh + head * F_OUT + oc;
        float s[4] = {}, nn[4] = {};
        #pragma unroll
        for (int r = 0; r < 4; r++) {
            #pragma unroll
            for (int c = 0; c < 8; c++) {
                s[r]  = fmaf(acc[r][c], as[c], s[r]);
                nn[r] = fmaf(acc[r][c], an[c], nn[r]);
            }
        }
        #pragma unroll
        for (int off = 4; off >= 1; off >>= 1) {
            #pragma unroll
            for (int r = 0; r < 4; r++) {
                s[r]  += __shfl_xor_sync(0xFFFFFFFFu, s[r], off);
                nn[r] += __shfl_xor_sync(0xFFFFFFFFu, nn[r], off);
            }
        }
        if ((tx & 7) == 0) {
            #pragma unroll
            for (int r = 0; r < 4; r++) {
                size_t idx = ((size_t)b * N_ + n0 + ty * 4 + r) * H_ + head;
                g_atts2[idx] = s[r];
                g_attn2[idx] = nn[r];
            }
        }
    }

    // ---- epilogue 2: fp16 h store (one 16B store per row) ----
    #pragma unroll
    for (int r = 0; r < 4; r++) {
        int n = n0 + ty * 4 + r;
        __half2 h0 = __floats2half2_rn(acc[r][0], acc[r][1]);
        __half2 h1 = __floats2half2_rn(acc[r][2], acc[r][3]);
        __half2 h2 = __floats2half2_rn(acc[r][4], acc[r][5]);
        __half2 h3 = __floats2half2_rn(acc[r][6], acc[r][7]);
        uint4 pk;
        pk.x = *(unsigned*)&h0;
        pk.y = *(unsigned*)&h1;
        pk.z = *(unsigned*)&h2;
        pk.w = *(unsigned*)&h3;
        *(uint4*)(g_h16 + ((size_t)b * N_ + n) * HF + head * F_OUT + oc) = pk;
    }
}

// -------------------------------------------------------------------------
// Kernel 2: fused A-row compaction + sparse gather-aggregate (R7 best, unchanged).
// -------------------------------------------------------------------------
__global__ __launch_bounds__(256) void agg_kernel(const float* __restrict__ A,
                                                  float* __restrict__ out) {
    const int bi = blockIdx.x;          // b*N + i
    const int b  = bi >> 11;
    const int t  = threadIdx.x;
    const int h  = t >> 5;              // warp id == head in gather phases
    const int l  = t & 31;

    __shared__ int   idx_s[DEG_CAP];
    __shared__ float w_s[DEG_CAP][8];
    __shared__ float atts_s[8];
    __shared__ int   wcnt[8];

    // ---- phase 0: compact adjacency row into idx_s ----
    {
        const float* Arow = A + (size_t)bi * N_;
        const int base_col = h * 256 + l * 8;
        float4 va = *(const float4*)(Arow + base_col);
        float4 vb = *(const float4*)(Arow + base_col + 4);
        unsigned m8 = (va.x != 0.0f ? 1u   : 0u) | (va.y != 0.0f ? 2u   : 0u) |
                      (va.z != 0.0f ? 4u   : 0u) | (va.w != 0.0f ? 8u   : 0u) |
                      (vb.x != 0.0f ? 16u  : 0u) | (vb.y != 0.0f ? 32u  : 0u) |
                      (vb.z != 0.0f ? 64u  : 0u) | (vb.w != 0.0f ? 128u : 0u);
        int cnt  = __popc(m8);
        int incl = cnt;
        #pragma unroll
        for (int off = 1; off < 32; off <<= 1) {
            int o = __shfl_up_sync(0xFFFFFFFFu, incl, off);
            if (l >= off) incl += o;
        }
        if (l == 31) wcnt[h] = incl;           // warp total
        int excl = incl - cnt;
        __syncthreads();

        int woff = 0;
        #pragma unroll
        for (int ww = 0; ww < 8; ww++) if (ww < h) woff += wcnt[ww];

        int pos = woff + excl;
        unsigned mm = m8;
        while (mm) {
            int bit = __ffs(mm) - 1;
            mm &= mm - 1u;
            if (pos < DEG_CAP) idx_s[pos] = base_col + bit;
            pos++;
        }
    }
    if (t < 8) atts_s[t] = g_atts2[(size_t)bi * 8 + t];
    __syncthreads();

    int deg = wcnt[0] + wcnt[1] + wcnt[2] + wcnt[3] +
              wcnt[4] + wcnt[5] + wcnt[6] + wcnt[7];
    deg = deg < DEG_CAP ? deg : DEG_CAP;
    const int deg4 = (deg + 3) & ~3;

    // ---- phase 1: weights for all (neighbor, head); pad [deg, deg4) ----
    if (t < deg) {
        int j = idx_s[t];
        const float* an = g_attn2 + ((size_t)(b * N_) + j) * 8;
        float4 a0 = *(const float4*)an;
        float4 a1 = *(const float4*)(an + 4);
        float vals[8] = {a0.x, a0.y, a0.z, a0.w, a1.x, a1.y, a1.z, a1.w};
        float w[8];
        #pragma unroll
        for (int hh = 0; hh < 8; hh++) {
            float x  = atts_s[hh] + vals[hh];
            float sc = fmaxf(x, 0.2f * x);
            w[hh] = __expf(sc);
        }
        *(float4*)&w_s[t][0] = make_float4(w[0], w[1], w[2], w[3]);
        *(float4*)&w_s[t][4] = make_float4(w[4], w[5], w[6], w[7]);
    } else if (t < deg4) {
        idx_s[t] = 0;
        *(float4*)&w_s[t][0] = make_float4(0.f, 0.f, 0.f, 0.f);
        *(float4*)&w_s[t][4] = make_float4(0.f, 0.f, 0.f, 0.f);
    }
    __syncthreads();

    // ---- phase 2: gather + weighted sum. grp = l>>3 picks 1 of 4 nbrs ----
    const int grp = l >> 3;
    const int q8  = (l & 7) * 8;     // 8 halves per lane
    const __half* hb = g_h16 + ((size_t)b * N_) * HF + h * F_OUT + q8;

    float acc[8] = {};
    float dacc = 0.f;

    for (int k = 0; k < deg4; k += 4) {
        int   j = idx_s[k + grp];
        float w = w_s[k + grp][h];
        uint4 v = *(const uint4*)(hb + (unsigned)j * HF);
        float2 f01 = __half22float2(*(__half2*)&v.x);
        float2 f23 = __half22float2(*(__half2*)&v.y);
        float2 f45 = __half22float2(*(__half2*)&v.z);
        float2 f67 = __half22float2(*(__half2*)&v.w);
        acc[0] = fmaf(w, f01.x, acc[0]); acc[1] = fmaf(w, f01.y, acc[1]);
        acc[2] = fmaf(w, f23.x, acc[2]); acc[3] = fmaf(w, f23.y, acc[3]);
        acc[4] = fmaf(w, f45.x, acc[4]); acc[5] = fmaf(w, f45.y, acc[5]);
        acc[6] = fmaf(w, f67.x, acc[6]); acc[7] = fmaf(w, f67.y, acc[7]);
        dacc += w;
    }

    // combine the 4 neighbor-groups (and the denominator) across lanes
    #pragma unroll
    for (int c = 0; c < 8; c++) {
        acc[c] += __shfl_xor_sync(0xFFFFFFFFu, acc[c], 8);
        acc[c] += __shfl_xor_sync(0xFFFFFFFFu, acc[c], 16);
    }
    dacc += __shfl_xor_sync(0xFFFFFFFFu, dacc, 8);
    dacc += __shfl_xor_sync(0xFFFFFFFFu, dacc, 16);

    if (l < 8) {
        float inv = 1.0f / dacc;
        float4 o0, o1;
        o0.x = fmaxf(acc[0] * inv, 0.f); o0.y = fmaxf(acc[1] * inv, 0.f);
        o0.z = fmaxf(acc[2] * inv, 0.f); o0.w = fmaxf(acc[3] * inv, 0.f);
        o1.x = fmaxf(acc[4] * inv, 0.f); o1.y = fmaxf(acc[5] * inv, 0.f);
        o1.z = fmaxf(acc[6] * inv, 0.f); o1.w = fmaxf(acc[7] * inv, 0.f);
        float* op = out + (size_t)bi * HF + h * F_OUT + q8;
        *(float4*)op       = o0;
        *(float4*)(op + 4) = o1;
    }
}

// -------------------------------------------------------------------------
extern "C" void kernel_launch(void* const* d_in, const int* in_sizes, int n_in,
                              void* d_out, int out_size) {
    const float* X       = (const float*)d_in[0];
    const float* A       = (const float*)d_in[1];
    const float* W       = (const float*)d_in[2];
    const float* a_self  = (const float*)d_in[3];
    const float* a_neigh = (const float*)d_in[4];
    float* out = (float*)d_out;

    // 1) h = X @ W (2 heads/CTA) + fused att logits + fp16 h store
    gemm_h_kernel<<<dim3((N_ / 64) * B_, H_ / 2), 256>>>(X, W, a_self, a_neigh);

    // 2) fused adjacency compaction + sparse softmax aggregation + relu + concat
    agg_kernel<<<B_ * N_, 256>>>(A, out);
}

// round 12
// speedup vs baseline: 1.0904x; 1.0904x over previous
#include <cuda_runtime.h>
#include <cuda_fp16.h>

#define B_    4
#define N_    2048
#define F_IN  256
#define H_    8
#define F_OUT 64
#define HF    (H_ * F_OUT)       // 512
#define DEG_CAP 256

// Scratch (device globals: allocation-free per harness rules)
__device__ __half g_h16[(size_t)B_ * N_ * HF];     // [b][n][h][o], fp16
__device__ float  g_atts2[B_ * N_ * H_];           // [b][n][h]
__device__ float  g_attn2[B_ * N_ * H_];           // [b][n][h]
__device__ int    g_deg[B_ * N_];
__device__ int    g_nbr[(size_t)B_ * N_ * DEG_CAP];

// -------------------------------------------------------------------------
// Kernel 1 (fat): even CTAs run the h-GEMM (R4-best 64x64, 4x4 micro-tile,
// fused logits + fp16 store); odd CTAs compact adjacency rows into g_nbr.
// Interleaving puts DRAM-bound nbr CTAs and FMA-bound gemm CTAs in the same
// wave, hiding the adjacency scan under the GEMM's idle DRAM pipe.
// -------------------------------------------------------------------------
__global__ __launch_bounds__(256) void pre_kernel(const float* __restrict__ X,
                                                  const float* __restrict__ W,
                                                  const float* __restrict__ a_self,
                                                  const float* __restrict__ a_neigh,
                                                  const float* __restrict__ A) {
    const int t = threadIdx.x;

    if (blockIdx.x & 1) {
        // ---------------- nbr role: 8 warps, one (b,i) row each ----------------
        int warp = (blockIdx.x >> 1) * 8 + (t >> 5);
        int lane = t & 31;
        const float* row = A + (size_t)warp * N_;
        int* outp = g_nbr + (size_t)warp * DEG_CAP;
        int base = 0;
        for (int c = 0; c < N_; c += 128) {
            float4 v = *(const float4*)(row + c + lane * 4);
            unsigned mx = __ballot_sync(0xFFFFFFFFu, v.x != 0.0f);
            unsigned my = __ballot_sync(0xFFFFFFFFu, v.y != 0.0f);
            unsigned mz = __ballot_sync(0xFFFFFFFFu, v.z != 0.0f);
            unsigned mw = __ballot_sync(0xFFFFFFFFu, v.w != 0.0f);
            unsigned lt = (1u << lane) - 1u;
            int cx = __popc(mx), cy = __popc(my), cz = __popc(mz), cw = __popc(mw);
            int col = c + lane * 4;
            if (v.x != 0.0f) { int p = base + __popc(mx & lt);                if (p < DEG_CAP) outp[p] = col;     }
            if (v.y != 0.0f) { int p = base + cx + __popc(my & lt);           if (p < DEG_CAP) outp[p] = col + 1; }
            if (v.z != 0.0f) { int p = base + cx + cy + __popc(mz & lt);      if (p < DEG_CAP) outp[p] = col + 2; }
            if (v.w != 0.0f) { int p = base + cx + cy + cz + __popc(mw & lt); if (p < DEG_CAP) outp[p] = col + 3; }
            base += cx + cy + cz + cw;
        }
        if (lane == 0) g_deg[warp] = base < DEG_CAP ? base : DEG_CAP;
        return;
    }

    // ---------------- gemm role (R4-best) ----------------
    const int cta  = blockIdx.x >> 1;      // 0..1023
    const int head = cta >> 7;
    const int rem  = cta & 127;
    const int b    = rem >> 5;
    const int n0   = (rem & 31) * 64;

    __shared__ float Xs[64][20];
    __shared__ float Ws[16][64];

    const int ty = t >> 4;
    const int tx = t & 15;

    const float* Xb = X + ((size_t)b * N_ + n0) * F_IN;
    const float* Wh = W + (size_t)head * F_IN * F_OUT;

    float acc[4][4] = {};

    for (int k0 = 0; k0 < F_IN; k0 += 16) {
        {
            int row = t >> 2;
            int q   = (t & 3) * 4;
            float4 v = *(const float4*)(Xb + (size_t)row * F_IN + k0 + q);
            *(float4*)&Xs[row][q] = v;
        }
        {
            int r = t >> 4;
            int q = (t & 15) * 4;
            *(float4*)&Ws[r][q] = *(const float4*)(Wh + (size_t)(k0 + r) * F_OUT + q);
        }
        __syncthreads();

        #pragma unroll
        for (int k = 0; k < 16; k++) {
            float a0 = Xs[ty * 4 + 0][k];
            float a1 = Xs[ty * 4 + 1][k];
            float a2 = Xs[ty * 4 + 2][k];
            float a3 = Xs[ty * 4 + 3][k];
            float4 bv = *(float4*)&Ws[k][tx * 4];
            acc[0][0] = fmaf(a0, bv.x, acc[0][0]); acc[0][1] = fmaf(a0, bv.y, acc[0][1]);
            acc[0][2] = fmaf(a0, bv.z, acc[0][2]); acc[0][3] = fmaf(a0, bv.w, acc[0][3]);
            acc[1][0] = fmaf(a1, bv.x, acc[1][0]); acc[1][1] = fmaf(a1, bv.y, acc[1][1]);
            acc[1][2] = fmaf(a1, bv.z, acc[1][2]); acc[1][3] = fmaf(a1, bv.w, acc[1][3]);
            acc[2][0] = fmaf(a2, bv.x, acc[2][0]); acc[2][1] = fmaf(a2, bv.y, acc[2][1]);
            acc[2][2] = fmaf(a2, bv.z, acc[2][2]); acc[2][3] = fmaf(a2, bv.w, acc[2][3]);
            acc[3][0] = fmaf(a3, bv.x, acc[3][0]); acc[3][1] = fmaf(a3, bv.y, acc[3][1]);
            acc[3][2] = fmaf(a3, bv.z, acc[3][2]); acc[3][3] = fmaf(a3, bv.w, acc[3][3]);
        }
        __syncthreads();
    }

    // ---- epilogue 1: attention logits from fp32 accumulators ----
    {
        const float* as = a_self  + head * F_OUT;
        const float* an = a_neigh + head * F_OUT;
        float s[4] = {}, nn[4] = {};
        #pragma unroll
        for (int r = 0; r < 4; r++) {
            #pragma unroll
            for (int c = 0; c < 4; c++) {
                s[r]  = fmaf(acc[r][c], as[tx * 4 + c], s[r]);
                nn[r] = fmaf(acc[r][c], an[tx * 4 + c], nn[r]);
            }
        }
        #pragma unroll
        for (int off = 8; off >= 1; off >>= 1) {
            #pragma unroll
            for (int r = 0; r < 4; r++) {
                s[r]  += __shfl_xor_sync(0xFFFFFFFFu, s[r], off);
                nn[r] += __shfl_xor_sync(0xFFFFFFFFu, nn[r], off);
            }
        }
        if (tx == 0) {
            #pragma unroll
            for (int r = 0; r < 4; r++) {
                size_t idx = ((size_t)b * N_ + n0 + ty * 4 + r) * H_ + head;
                g_atts2[idx] = s[r];
                g_attn2[idx] = nn[r];
            }
        }
    }

    // ---- epilogue 2: fp16 h store to [b][n][h][o] ----
    #pragma unroll
    for (int r = 0; r < 4; r++) {
        int n = n0 + ty * 4 + r;
        __half2 p0 = __floats2half2_rn(acc[r][0], acc[r][1]);
        __half2 p1 = __floats2half2_rn(acc[r][2], acc[r][3]);
        __half2* dst = (__half2*)(g_h16 + ((size_t)b * N_ + n) * HF + head * F_OUT + tx * 4);
        dst[0] = p0;
        dst[1] = p1;
    }
}

// -------------------------------------------------------------------------
// Kernel 2: sparse gather-aggregate, fp16 payload (R4 measured-best form).
// CTA = (b,i); warp = head. Lane l handles neighbor k+(l>>3), cols (l&7)*8.
// -------------------------------------------------------------------------
__global__ __launch_bounds__(256) void agg_kernel(float* __restrict__ out) {
    const int bi = blockIdx.x;          // b*N + i
    const int b  = bi >> 11;
    const int t  = threadIdx.x;
    const int h  = t >> 5;
    const int l  = t & 31;

    __shared__ int   idx_s[DEG_CAP];
    __shared__ float w_s[DEG_CAP][8];
    __shared__ float atts_s[8];

    const int deg  = g_deg[bi];
    const int deg4 = (deg + 3) & ~3;

    for (int k = t; k < deg; k += 256) idx_s[k] = g_nbr[(size_t)bi * DEG_CAP + k];
    if (t < 8) atts_s[t] = g_atts2[(size_t)bi * 8 + t];
    __syncthreads();

    // phase 1: weights for all (neighbor, head); pad [deg, deg4) with zeros
    if (t < deg) {
        int j = idx_s[t];
        const float* an = g_attn2 + ((size_t)(b * N_) + j) * 8;
        float4 a0 = *(const float4*)an;
        float4 a1 = *(const float4*)(an + 4);
        float vals[8] = {a0.x, a0.y, a0.z, a0.w, a1.x, a1.y, a1.z, a1.w};
        float w[8];
        #pragma unroll
        for (int hh = 0; hh < 8; hh++) {
            float x  = atts_s[hh] + vals[hh];
            float sc = fmaxf(x, 0.2f * x);
            w[hh] = __expf(sc);
        }
        *(float4*)&w_s[t][0] = make_float4(w[0], w[1], w[2], w[3]);
        *(float4*)&w_s[t][4] = make_float4(w[4], w[5], w[6], w[7]);
    } else if (t < deg4) {
        idx_s[t] = 0;
        *(float4*)&w_s[t][0] = make_float4(0.f, 0.f, 0.f, 0.f);
        *(float4*)&w_s[t][4] = make_float4(0.f, 0.f, 0.f, 0.f);
    }
    __syncthreads();

    // phase 2: gather + weighted sum. grp = l>>3 selects one of 4 neighbors.
    const int grp = l >> 3;
    const int q8  = (l & 7) * 8;     // 8 halves per lane
    const __half* hb = g_h16 + ((size_t)b * N_) * HF + h * F_OUT + q8;

    float acc[8] = {};
    float dacc = 0.f;

    for (int k = 0; k < deg4; k += 4) {
        int   j = idx_s[k + grp];
        float w = w_s[k + grp][h];
        uint4 v = *(const uint4*)(hb + (unsigned)j * HF);
        float2 f01 = __half22float2(*(__half2*)&v.x);
        float2 f23 = __half22float2(*(__half2*)&v.y);
        float2 f45 = __half22float2(*(__half2*)&v.z);
        float2 f67 = __half22float2(*(__half2*)&v.w);
        acc[0] = fmaf(w, f01.x, acc[0]); acc[1] = fmaf(w, f01.y, acc[1]);
        acc[2] = fmaf(w, f23.x, acc[2]); acc[3] = fmaf(w, f23.y, acc[3]);
        acc[4] = fmaf(w, f45.x, acc[4]); acc[5] = fmaf(w, f45.y, acc[5]);
        acc[6] = fmaf(w, f67.x, acc[6]); acc[7] = fmaf(w, f67.y, acc[7]);
        dacc += w;
    }

    // combine the 4 neighbor-groups (and the denominator) across lanes
    #pragma unroll
    for (int c = 0; c < 8; c++) {
        acc[c] += __shfl_xor_sync(0xFFFFFFFFu, acc[c], 8);
        acc[c] += __shfl_xor_sync(0xFFFFFFFFu, acc[c], 16);
    }
    dacc += __shfl_xor_sync(0xFFFFFFFFu, dacc, 8);
    dacc += __shfl_xor_sync(0xFFFFFFFFu, dacc, 16);

    if (l < 8) {
        float inv = 1.0f / dacc;
        float4 o0, o1;
        o0.x = fmaxf(acc[0] * inv, 0.f); o0.y = fmaxf(acc[1] * inv, 0.f);
        o0.z = fmaxf(acc[2] * inv, 0.f); o0.w = fmaxf(acc[3] * inv, 0.f);
        o1.x = fmaxf(acc[4] * inv, 0.f); o1.y = fmaxf(acc[5] * inv, 0.f);
        o1.z = fmaxf(acc[6] * inv, 0.f); o1.w = fmaxf(acc[7] * inv, 0.f);
        float* op = out + (size_t)bi * HF + h * F_OUT + q8;
        *(float4*)op       = o0;
        *(float4*)(op + 4) = o1;
    }
}

// -------------------------------------------------------------------------
extern "C" void kernel_launch(void* const* d_in, const int* in_sizes, int n_in,
                              void* d_out, int out_size) {
    const float* X       = (const float*)d_in[0];
    const float* A       = (const float*)d_in[1];
    const float* W       = (const float*)d_in[2];
    const float* a_self  = (const float*)d_in[3];
    const float* a_neigh = (const float*)d_in[4];
    float* out = (float*)d_out;

    // 1) fat kernel: h-GEMM (even CTAs) overlapped with adjacency compaction (odd CTAs)
    pre_kernel<<<2048, 256>>>(X, W, a_self, a_neigh, A);

    // 2) sparse masked-softmax aggregation + relu + concat
    agg_kernel<<<B_ * N_, 256>>>(out);
}

// round 13
// speedup vs baseline: 1.4686x; 1.3468x over previous
#include <cuda_runtime.h>
#include <cuda_fp16.h>

#define B_    4
#define N_    2048
#define F_IN  256
#define H_    8
#define F_OUT 64
#define HF    (H_ * F_OUT)       // 512
#define DEG_CAP 256

// Scratch (device globals: allocation-free per harness rules)
__device__ __half g_h16[(size_t)B_ * N_ * HF];     // [b][n][h][o], fp16
__device__ float  g_atts2[B_ * N_ * H_];           // [b][n][h]
__device__ float  g_attn2[B_ * N_ * H_];           // [b][n][h]

__device__ __forceinline__ unsigned f2tf32(float f) {
    unsigned r;
    asm("cvt.rna.tf32.f32 %0, %1;" : "=r"(r) : "f"(f));
    return r;
}

// -------------------------------------------------------------------------
// Kernel 1: h = X @ W per head via tf32 mma.sync (m16n8k8), fp32 accum.
// CTA = 64 rows x 64 cols (one head). 8 warps in 4x2 (16-row x 32-col each).
// Epilogue: stage fp32 h tile in smem -> att logits + fp16 h store.
// -------------------------------------------------------------------------
__global__ __launch_bounds__(256) void gemm_h_tc(const float* __restrict__ X,
                                                 const float* __restrict__ W,
                                                 const float* __restrict__ a_self,
                                                 const float* __restrict__ a_neigh) {
    const int head = blockIdx.y;
    const int b    = blockIdx.x >> 5;
    const int n0   = (blockIdx.x & 31) * 64;

    __shared__ unsigned Xs[64][36];    // tf32 bits, 64 rows x 32 k (pad 36)
    __shared__ unsigned Wsm[32][72];   // tf32 bits, 32 k x 64 o (pad 72)
    __shared__ float    hs[64][66];    // fp32 h tile for epilogue

    const int t    = threadIdx.x;
    const int lane = t & 31;
    const int warp = t >> 5;
    const int wm   = warp >> 1;        // 0..3 -> rows wm*16..+15
    const int wn   = warp & 1;         // 0..1 -> cols wn*32..+31
    const int g    = lane >> 2;        // groupID 0..7
    const int tg   = lane & 3;         // threadID_in_group 0..3

    const float* Xb = X + ((size_t)b * N_ + n0) * F_IN;
    const float* Wh = W + (size_t)head * F_IN * F_OUT;

    float c[4][4] = {};                // [ntile][frag]

    for (int k0 = 0; k0 < F_IN; k0 += 32) {
        {   // X chunk 64x32 -> tf32 smem
            int row = t >> 2;
            int q   = (t & 3) * 8;
            const float* src = Xb + (size_t)row * F_IN + k0 + q;
            float4 u0 = *(const float4*)src;
            float4 u1 = *(const float4*)(src + 4);
            Xs[row][q + 0] = f2tf32(u0.x); Xs[row][q + 1] = f2tf32(u0.y);
            Xs[row][q + 2] = f2tf32(u0.z); Xs[row][q + 3] = f2tf32(u0.w);
            Xs[row][q + 4] = f2tf32(u1.x); Xs[row][q + 5] = f2tf32(u1.y);
            Xs[row][q + 6] = f2tf32(u1.z); Xs[row][q + 7] = f2tf32(u1.w);
        }
        {   // W chunk 32x64 -> tf32 smem
            int r = t >> 3;
            int q = (t & 7) * 8;
            const float* src = Wh + (size_t)(k0 + r) * F_OUT + q;
            float4 u0 = *(const float4*)src;
            float4 u1 = *(const float4*)(src + 4);
            Wsm[r][q + 0] = f2tf32(u0.x); Wsm[r][q + 1] = f2tf32(u0.y);
            Wsm[r][q + 2] = f2tf32(u0.z); Wsm[r][q + 3] = f2tf32(u0.w);
            Wsm[r][q + 4] = f2tf32(u1.x); Wsm[r][q + 5] = f2tf32(u1.y);
            Wsm[r][q + 6] = f2tf32(u1.z); Wsm[r][q + 7] = f2tf32(u1.w);
        }
        __syncthreads();

        #pragma unroll
        for (int ks = 0; ks < 4; ks++) {
            unsigned a0 = Xs[wm * 16 + g][ks * 8 + tg];
            unsigned a1 = Xs[wm * 16 + g + 8][ks * 8 + tg];
            unsigned a2 = Xs[wm * 16 + g][ks * 8 + tg + 4];
            unsigned a3 = Xs[wm * 16 + g + 8][ks * 8 + tg + 4];
            #pragma unroll
            for (int nt = 0; nt < 4; nt++) {
                unsigned b0 = Wsm[ks * 8 + tg][wn * 32 + nt * 8 + g];
                unsigned b1 = Wsm[ks * 8 + tg + 4][wn * 32 + nt * 8 + g];
                asm volatile(
                    "mma.sync.aligned.m16n8k8.row.col.f32.tf32.tf32.f32 "
                    "{%0,%1,%2,%3}, {%4,%5,%6,%7}, {%8,%9}, {%0,%1,%2,%3};"
                    : "+f"(c[nt][0]), "+f"(c[nt][1]), "+f"(c[nt][2]), "+f"(c[nt][3])
                    : "r"(a0), "r"(a1), "r"(a2), "r"(a3), "r"(b0), "r"(b1));
            }
        }
        __syncthreads();
    }

    // store C fragments to fp32 smem tile
    {
        int row = wm * 16 + g;
        #pragma unroll
        for (int nt = 0; nt < 4; nt++) {
            int col = wn * 32 + nt * 8 + tg * 2;
            hs[row][col]     = c[nt][0];
            hs[row][col + 1] = c[nt][1];
            hs[row + 8][col]     = c[nt][2];
            hs[row + 8][col + 1] = c[nt][3];
        }
    }
    __syncthreads();

    // epilogue: logits + fp16 store. thread t: row t>>2, 16-col segment (t&3)*16
    {
        int row = t >> 2;
        int seg = (t & 3) * 16;
        const float* as = a_self  + head * F_OUT + seg;
        const float* an = a_neigh + head * F_OUT + seg;
        float v[16];
        float s = 0.f, nn = 0.f;
        #pragma unroll
        for (int cc = 0; cc < 16; cc++) {
            v[cc] = hs[row][seg + cc];
            s  = fmaf(v[cc], as[cc], s);
            nn = fmaf(v[cc], an[cc], nn);
        }
        s  += __shfl_xor_sync(0xFFFFFFFFu, s, 1);
        s  += __shfl_xor_sync(0xFFFFFFFFu, s, 2);
        nn += __shfl_xor_sync(0xFFFFFFFFu, nn, 1);
        nn += __shfl_xor_sync(0xFFFFFFFFu, nn, 2);
        if ((t & 3) == 0) {
            size_t idx = ((size_t)b * N_ + n0 + row) * H_ + head;
            g_atts2[idx] = s;
            g_attn2[idx] = nn;
        }

        __half2 hh[8];
        #pragma unroll
        for (int i = 0; i < 8; i++) hh[i] = __floats2half2_rn(v[2 * i], v[2 * i + 1]);
        uint4 p0, p1;
        p0.x = *(unsigned*)&hh[0]; p0.y = *(unsigned*)&hh[1];
        p0.z = *(unsigned*)&hh[2]; p0.w = *(unsigned*)&hh[3];
        p1.x = *(unsigned*)&hh[4]; p1.y = *(unsigned*)&hh[5];
        p1.z = *(unsigned*)&hh[6]; p1.w = *(unsigned*)&hh[7];
        __half* dst = g_h16 + ((size_t)b * N_ + n0 + row) * HF + head * F_OUT + seg;
        *(uint4*)dst       = p0;
        *(uint4*)(dst + 8) = p1;
    }
}

// -------------------------------------------------------------------------
// Kernel 2: fused A-row compaction + sparse gather-aggregate (R7 best, unchanged).
// -------------------------------------------------------------------------
__global__ __launch_bounds__(256) void agg_kernel(const float* __restrict__ A,
                                                  float* __restrict__ out) {
    const int bi = blockIdx.x;          // b*N + i
    const int b  = bi >> 11;
    const int t  = threadIdx.x;
    const int h  = t >> 5;              // warp id == head in gather phases
    const int l  = t & 31;

    __shared__ int   idx_s[DEG_CAP];
    __shared__ float w_s[DEG_CAP][8];
    __shared__ float atts_s[8];
    __shared__ int   wcnt[8];

    // ---- phase 0: compact adjacency row into idx_s ----
    {
        const float* Arow = A + (size_t)bi * N_;
        const int base_col = h * 256 + l * 8;
        float4 va = *(const float4*)(Arow + base_col);
        float4 vb = *(const float4*)(Arow + base_col + 4);
        unsigned m8 = (va.x != 0.0f ? 1u   : 0u) | (va.y != 0.0f ? 2u   : 0u) |
                      (va.z != 0.0f ? 4u   : 0u) | (va.w != 0.0f ? 8u   : 0u) |
                      (vb.x != 0.0f ? 16u  : 0u) | (vb.y != 0.0f ? 32u  : 0u) |
                      (vb.z != 0.0f ? 64u  : 0u) | (vb.w != 0.0f ? 128u : 0u);
        int cnt  = __popc(m8);
        int incl = cnt;
        #pragma unroll
        for (int off = 1; off < 32; off <<= 1) {
            int o = __shfl_up_sync(0xFFFFFFFFu, incl, off);
            if (l >= off) incl += o;
        }
        if (l == 31) wcnt[h] = incl;           // warp total
        int excl = incl - cnt;
        __syncthreads();

        int woff = 0;
        #pragma unroll
        for (int ww = 0; ww < 8; ww++) if (ww < h) woff += wcnt[ww];

        int pos = woff + excl;
        unsigned mm = m8;
        while (mm) {
            int bit = __ffs(mm) - 1;
            mm &= mm - 1u;
            if (pos < DEG_CAP) idx_s[pos] = base_col + bit;
            pos++;
        }
    }
    if (t < 8) atts_s[t] = g_atts2[(size_t)bi * 8 + t];
    __syncthreads();

    int deg = wcnt[0] + wcnt[1] + wcnt[2] + wcnt[3] +
              wcnt[4] + wcnt[5] + wcnt[6] + wcnt[7];
    deg = deg < DEG_CAP ? deg : DEG_CAP;
    const int deg4 = (deg + 3) & ~3;

    // ---- phase 1: weights for all (neighbor, head); pad [deg, deg4) ----
    if (t < deg) {
        int j = idx_s[t];
        const float* an = g_attn2 + ((size_t)(b * N_) + j) * 8;
        float4 a0 = *(const float4*)an;
        float4 a1 = *(const float4*)(an + 4);
        float vals[8] = {a0.x, a0.y, a0.z, a0.w, a1.x, a1.y, a1.z, a1.w};
        float w[8];
        #pragma unroll
        for (int hh = 0; hh < 8; hh++) {
            float x  = atts_s[hh] + vals[hh];
            float sc = fmaxf(x, 0.2f * x);
            w[hh] = __expf(sc);
        }
        *(float4*)&w_s[t][0] = make_float4(w[0], w[1], w[2], w[3]);
        *(float4*)&w_s[t][4] = make_float4(w[4], w[5], w[6], w[7]);
    } else if (t < deg4) {
        idx_s[t] = 0;
        *(float4*)&w_s[t][0] = make_float4(0.f, 0.f, 0.f, 0.f);
        *(float4*)&w_s[t][4] = make_float4(0.f, 0.f, 0.f, 0.f);
    }
    __syncthreads();

    // ---- phase 2: gather + weighted sum. grp = l>>3 picks 1 of 4 nbrs ----
    const int grp = l >> 3;
    const int q8  = (l & 7) * 8;     // 8 halves per lane
    const __half* hb = g_h16 + ((size_t)b * N_) * HF + h * F_OUT + q8;

    float acc[8] = {};
    float dacc = 0.f;

    for (int k = 0; k < deg4; k += 4) {
        int   j = idx_s[k + grp];
        float w = w_s[k + grp][h];
        uint4 v = *(const uint4*)(hb + (unsigned)j * HF);
        float2 f01 = __half22float2(*(__half2*)&v.x);
        float2 f23 = __half22float2(*(__half2*)&v.y);
        float2 f45 = __half22float2(*(__half2*)&v.z);
        float2 f67 = __half22float2(*(__half2*)&v.w);
        acc[0] = fmaf(w, f01.x, acc[0]); acc[1] = fmaf(w, f01.y, acc[1]);
        acc[2] = fmaf(w, f23.x, acc[2]); acc[3] = fmaf(w, f23.y, acc[3]);
        acc[4] = fmaf(w, f45.x, acc[4]); acc[5] = fmaf(w, f45.y, acc[5]);
        acc[6] = fmaf(w, f67.x, acc[6]); acc[7] = fmaf(w, f67.y, acc[7]);
        dacc += w;
    }

    // combine the 4 neighbor-groups (and the denominator) across lanes
    #pragma unroll
    for (int c = 0; c < 8; c++) {
        acc[c] += __shfl_xor_sync(0xFFFFFFFFu, acc[c], 8);
        acc[c] += __shfl_xor_sync(0xFFFFFFFFu, acc[c], 16);
    }
    dacc += __shfl_xor_sync(0xFFFFFFFFu, dacc, 8);
    dacc += __shfl_xor_sync(0xFFFFFFFFu, dacc, 16);

    if (l < 8) {
        float inv = 1.0f / dacc;
        float4 o0, o1;
        o0.x = fmaxf(acc[0] * inv, 0.f); o0.y = fmaxf(acc[1] * inv, 0.f);
        o0.z = fmaxf(acc[2] * inv, 0.f); o0.w = fmaxf(acc[3] * inv, 0.f);
        o1.x = fmaxf(acc[4] * inv, 0.f); o1.y = fmaxf(acc[5] * inv, 0.f);
        o1.z = fmaxf(acc[6] * inv, 0.f); o1.w = fmaxf(acc[7] * inv, 0.f);
        float* op = out + (size_t)bi * HF + h * F_OUT + q8;
        *(float4*)op       = o0;
        *(float4*)(op + 4) = o1;
    }
}

// -------------------------------------------------------------------------
extern "C" void kernel_launch(void* const* d_in, const int* in_sizes, int n_in,
                              void* d_out, int out_size) {
    const float* X       = (const float*)d_in[0];
    const float* A       = (const float*)d_in[1];
    const float* W       = (const float*)d_in[2];
    const float* a_self  = (const float*)d_in[3];
    const float* a_neigh = (const float*)d_in[4];
    float* out = (float*)d_out;

    // 1) h = X @ W per head (tf32 tensor cores) + fused logits + fp16 h store
    gemm_h_tc<<<dim3(32 * B_, H_), 256>>>(X, W, a_self, a_neigh);

    // 2) fused adjacency compaction + sparse softmax aggregation + relu + concat
    agg_kernel<<<B_ * N_, 256>>>(A, out);
}